// round 2
// baseline (speedup 1.0000x reference)
#include <cuda_runtime.h>
#include <math.h>

// ============================================================================
// LSTM: T=48, B=4096, H=256.
//   x[t,b,:]  = inputs[t,b]*inp_W + inp_b                (rank-1)
//   gx[t,b,:] = s_tb*v1 + v0   where v1=W_ih@inp_W, v0=W_ih@inp_b+b_ih+b_hh
//   gates     = gx + h@W_hh^T ; i,f,g,o quarters; c=f*c+i*tanh(g); h=o*tanh(c)
//   out[b]    = h_final[b]@out_W^T + out_b
// Batch rows are independent -> persistent CTA owns MB=32 rows for all T steps.
// c state lives in registers; h state ping-pongs in smem; W_hh streamed from
// L2 into smem tiles each step.
// ============================================================================

#define T_STEPS 48
#define BATCH   4096
#define HID     256
#define G4      1024
#define MB      32
#define KC      64
#define WSS     68            // W_s row stride in floats (64 + 4 pad)
#define NTHREADS 256
#define NBLOCKS (BATCH / MB)  // 128

// smem layout (float offsets)
#define OFF_HA  0
#define OFF_HB  (MB * HID)                 // 8192
#define OFF_WS  (2 * MB * HID)             // 16384
#define OFF_V0  (OFF_WS + 256 * WSS)       // +17408
#define OFF_V1  (OFF_V0 + G4)
#define SMEM_FLOATS (OFF_V1 + G4)
#define SMEM_BYTES  (SMEM_FLOATS * 4)      // 143360 bytes

__device__ float d_v0[G4];
__device__ float d_v1[G4];

// ---------------------------------------------------------------------------
// Precompute v0, v1 (1024 dot products of length 256). Trivial cost.
// ---------------------------------------------------------------------------
__global__ void precompute_kernel(const float* __restrict__ inp_W,
                                  const float* __restrict__ inp_b,
                                  const float* __restrict__ W_ih,
                                  const float* __restrict__ b_ih,
                                  const float* __restrict__ b_hh) {
    int g = blockIdx.x * blockDim.x + threadIdx.x;
    if (g >= G4) return;
    const float* row = W_ih + g * HID;
    float a0 = 0.f, a1 = 0.f;
    #pragma unroll 4
    for (int k = 0; k < HID; k++) {
        float w = row[k];
        a1 = fmaf(w, inp_W[k], a1);
        a0 = fmaf(w, inp_b[k], a0);
    }
    d_v0[g] = a0 + b_ih[g] + b_hh[g];
    d_v1[g] = a1;
}

__device__ __forceinline__ float sigmoidf_(float x) {
    return 1.0f / (1.0f + __expf(-x));
}

// ---------------------------------------------------------------------------
// Persistent LSTM kernel. 128 CTAs x 256 threads, 1 CTA/SM.
// Thread tile: 4 batch rows x 2 hidden cols x 4 gates = 32 accumulators.
//   jt = lane (0..31) -> hidden col pair; bt = warp (0..7) -> 4 batch rows.
// Per step: 4 chunks of 64 hidden cols; per chunk, K=256 in 4 tiles of 64.
// ---------------------------------------------------------------------------
__global__ __launch_bounds__(NTHREADS, 1)
void lstm_kernel(const float* __restrict__ inputs,
                 const float* __restrict__ W_hh,
                 const float* __restrict__ out_W,
                 const float* __restrict__ out_b,
                 float* __restrict__ out) {
    extern __shared__ float smem[];
    float* h_a  = smem + OFF_HA;
    float* h_b  = smem + OFF_HB;
    float* W_s  = smem + OFF_WS;
    float* v0_s = smem + OFF_V0;
    float* v1_s = smem + OFF_V1;

    const int tid = threadIdx.x;
    const int jt  = tid & 31;     // lane -> hidden col pair
    const int bt  = tid >> 5;     // warp -> batch group
    const int b0  = bt * 4;
    const int bglob = blockIdx.x * MB;

    for (int i = tid; i < MB * HID; i += NTHREADS) h_a[i] = 0.f;
    for (int i = tid; i < G4; i += NTHREADS) { v0_s[i] = d_v0[i]; v1_s[i] = d_v1[i]; }

    float c[4][4][2];   // [chunk][bb][jj] cell state, registers only
    #pragma unroll
    for (int cn = 0; cn < 4; cn++)
        #pragma unroll
        for (int bb = 0; bb < 4; bb++)
            #pragma unroll
            for (int jj = 0; jj < 2; jj++) c[cn][bb][jj] = 0.f;

    float* h_cur = h_a;
    float* h_nxt = h_b;
    __syncthreads();

    for (int t = 0; t < T_STEPS; t++) {
        float sv[4];
        #pragma unroll
        for (int bb = 0; bb < 4; bb++)
            sv[bb] = inputs[t * BATCH + bglob + b0 + bb];

        #pragma unroll 1
        for (int cn = 0; cn < 4; cn++) {
            // init accumulators with gx = v0 + s*v1
            float acc[4][2][4];   // [bb][jj][q]
            #pragma unroll
            for (int q = 0; q < 4; q++) {
                #pragma unroll
                for (int jj = 0; jj < 2; jj++) {
                    int g = q * 256 + cn * 64 + 2 * jt + jj;
                    float v0 = v0_s[g], v1 = v1_s[g];
                    #pragma unroll
                    for (int bb = 0; bb < 4; bb++)
                        acc[bb][jj][q] = fmaf(sv[bb], v1, v0);
                }
            }

            #pragma unroll 1
            for (int kt = 0; kt < HID / KC; kt++) {
                __syncthreads();   // previous tile consumers done
                // cooperative load of W tile: 256 rows (4 gates x 64 cols) x 64 k
                #pragma unroll 4
                for (int i = tid; i < 256 * KC; i += NTHREADS) {
                    int row = i >> 6;          // KC == 64
                    int k   = i & 63;
                    int q   = row >> 6;
                    int jl  = row & 63;
                    W_s[row * WSS + k] =
                        W_hh[(q * 256 + cn * 64 + jl) * HID + kt * KC + k];
                }
                __syncthreads();

                const float* hbase = h_cur + kt * KC;
                #pragma unroll 8
                for (int k4 = 0; k4 < KC; k4 += 4) {
                    float4 hv[4];
                    #pragma unroll
                    for (int bb = 0; bb < 4; bb++)
                        hv[bb] = *(const float4*)&hbase[(b0 + bb) * HID + k4];
                    #pragma unroll
                    for (int q = 0; q < 4; q++) {
                        #pragma unroll
                        for (int jj = 0; jj < 2; jj++) {
                            float4 w = *(const float4*)&W_s[(q * 64 + 2 * jt + jj) * WSS + k4];
                            #pragma unroll
                            for (int bb = 0; bb < 4; bb++) {
                                float a = acc[bb][jj][q];
                                a = fmaf(hv[bb].x, w.x, a);
                                a = fmaf(hv[bb].y, w.y, a);
                                a = fmaf(hv[bb].z, w.z, a);
                                a = fmaf(hv[bb].w, w.w, a);
                                acc[bb][jj][q] = a;
                            }
                        }
                    }
                }
            }

            // gate nonlinearities + state update for this chunk
            #pragma unroll
            for (int bb = 0; bb < 4; bb++) {
                #pragma unroll
                for (int jj = 0; jj < 2; jj++) {
                    float gi = sigmoidf_(acc[bb][jj][0]);
                    float gf = sigmoidf_(acc[bb][jj][1]);
                    float gg = tanhf(acc[bb][jj][2]);
                    float go = sigmoidf_(acc[bb][jj][3]);
                    float cc = fmaf(gf, c[cn][bb][jj], gi * gg);
                    c[cn][bb][jj] = cc;
                    h_nxt[(b0 + bb) * HID + cn * 64 + 2 * jt + jj] = go * tanhf(cc);
                }
            }
        }
        // swap buffers; the syncthreads at the top of the next kt loop makes
        // all h_nxt writes visible before anyone reads the new h_cur.
        float* tmp = h_cur; h_cur = h_nxt; h_nxt = tmp;
    }
    __syncthreads();

    // output projection: warp bt handles rows b0..b0+3
    float ob = out_b[0];
    #pragma unroll
    for (int bb = 0; bb < 4; bb++) {
        int b = b0 + bb;
        float sum = 0.f;
        #pragma unroll
        for (int k = jt; k < HID; k += 32)
            sum = fmaf(h_cur[b * HID + k], out_W[k], sum);
        #pragma unroll
        for (int off = 16; off; off >>= 1)
            sum += __shfl_xor_sync(0xffffffffu, sum, off);
        if (jt == 0) out[bglob + b] = sum + ob;
    }
}

// ---------------------------------------------------------------------------
extern "C" void kernel_launch(void* const* d_in, const int* in_sizes, int n_in,
                              void* d_out, int out_size) {
    const float* inputs = (const float*)d_in[0];
    const float* inp_W  = (const float*)d_in[1];
    const float* inp_b  = (const float*)d_in[2];
    const float* W_ih   = (const float*)d_in[3];
    const float* W_hh   = (const float*)d_in[4];
    const float* b_ih   = (const float*)d_in[5];
    const float* b_hh   = (const float*)d_in[6];
    const float* out_W  = (const float*)d_in[7];
    const float* out_b  = (const float*)d_in[8];
    float* out = (float*)d_out;

    cudaFuncSetAttribute(lstm_kernel,
                         cudaFuncAttributeMaxDynamicSharedMemorySize, SMEM_BYTES);

    precompute_kernel<<<(G4 + 127) / 128, 128>>>(inp_W, inp_b, W_ih, b_ih, b_hh);
    lstm_kernel<<<NBLOCKS, NTHREADS, SMEM_BYTES>>>(inputs, W_hh, out_W, out_b, out);
}